// round 13
// baseline (speedup 1.0000x reference)
#include <cuda_runtime.h>
#include <cuda_bf16.h>
#include <cstdint>
#include <math.h>

// ---------------------------------------------------------------------------
// Problem constants
// ---------------------------------------------------------------------------
#define LNUM 2
#define DMODEL 256
#define DFF 1024
#define NH 8
#define NP 4
#define CIN 512
#define BATCH 8
#define HH 64
#define WW 64
#define HW (HH * WW)            // 4096
#define MROWS (BATCH * HW)      // 32768
#define EPSV 1e-5f
#define NOA 96                  // merged offsets(64)+attn(32)

// ---------------------------------------------------------------------------
// Scratch (device globals; no dynamic allocation allowed)
// ---------------------------------------------------------------------------
__device__ float g_SRC[(size_t)MROWS * DMODEL];
__device__ float g_Q[(size_t)MROWS * DMODEL];
__device__ float g_VAL[(size_t)MROWS * DMODEL];
__device__ float g_T1[(size_t)MROWS * DMODEL];
__device__ float g_OA[(size_t)MROWS * NOA];
__device__ float g_H[(size_t)MROWS * DFF];
__device__ float g_WIT[CIN * DMODEL];    // W_in^T  [CIN][D]
__device__ float g_WOT[DMODEL * CIN];    // W_out^T [D][CIN]
__device__ float g_WOA[DMODEL * NOA];    // [k][n]
__device__ float g_bOA[NOA];
__device__ float g_alpha1[DMODEL], g_beta1[DMODEL];
__device__ float g_alpha2[CIN],    g_beta2[CIN];

// ---------------------------------------------------------------------------
// tf32 conversion (round-to-nearest)
// ---------------------------------------------------------------------------
__device__ __forceinline__ unsigned f2tf(float f)
{
    unsigned r;
    asm("cvt.rna.tf32.f32 %0, %1;" : "=r"(r) : "f"(f));
    return r;
}

// ---------------------------------------------------------------------------
// TF32 tensor-core GEMM, double-buffered smem.
//   C[M,N] = act((A[M,K] @ B[K,N]) * alpha[n] + beta[n])
// Block tile 128x128, BK=16, 8 warps (warp tile 64x32), mma.m16n8k8.
// __launch_bounds__(256, 2): cap regs for 2 CTAs/SM (4 warps/SMSP) so the
// HMMA pipe stays fed across syncs/staging/epilogue of either CTA.
// ACOL=1:  A is x-layout [b][k][hw]; staged as [k][m] (tile within one batch).
// OTRANS=1: epilogue restages via smem, writes out[b][c][hw] + BN+ReLU.
// ---------------------------------------------------------------------------
template<int ACOL, int OTRANS>
__global__ void __launch_bounds__(256, 2)
gemm_tf32_kernel(const float* __restrict__ A, const float* __restrict__ B,
                 float* __restrict__ C, int M, int N, int K,
                 const float* __restrict__ alpha, const float* __restrict__ beta,
                 int do_relu)
{
    // raw smem, aliased three ways
    __shared__ __align__(16) unsigned sraw[2 * 128 * 20 + 2 * 16 * 136];
    unsigned (*As)[128][20]  = (unsigned(*)[128][20])sraw;              // AROW
    unsigned (*Ask)[16][136] = (unsigned(*)[16][136])sraw;              // ACOL
    unsigned (*Bs)[16][136]  = (unsigned(*)[16][136])(sraw + 2 * 128 * 20);
    float    (*cbuf)[132]    = (float(*)[132])sraw;                     // OTRANS epi

    const int t    = threadIdx.x;
    const int bm   = blockIdx.y * 128;
    const int bn   = blockIdx.x * 128;
    const int warp = t >> 5;
    const int lane = t & 31;
    const int wm   = (warp & 1) * 64;
    const int wn   = (warp >> 1) * 32;
    const int gid  = lane >> 2;
    const int q    = lane & 3;

    const int a_r = t >> 2;
    const int a_c = (t & 3) * 4;
    const int b_r = t >> 5;
    const int b_c = (t & 31) * 4;

    const float* Axb = A;
    int hw0 = 0;
    if (ACOL) {
        int batch = bm >> 12;
        hw0 = bm & (HW - 1);
        Axb = A + (size_t)batch * K * HW;
    }

    float4 ar[2], br[2];

    float acc[4][4][4];
    #pragma unroll
    for (int mi = 0; mi < 4; mi++)
        #pragma unroll
        for (int ni = 0; ni < 4; ni++)
            #pragma unroll
            for (int r = 0; r < 4; r++) acc[mi][ni][r] = 0.0f;

    const int nk = K >> 4;

    auto load_chunk = [&](int k0) {
        if (ACOL) {
            #pragma unroll
            for (int i = 0; i < 2; i++) {
                int idx = t + i * 256;
                int k   = idx >> 5;
                int mq  = (idx & 31) * 4;
                ar[i] = *(const float4*)(Axb + (size_t)(k0 + k) * HW + hw0 + mq);
            }
        } else {
            #pragma unroll
            for (int i = 0; i < 2; i++)
                ar[i] = *(const float4*)(A + (size_t)(bm + a_r + i * 64) * K + k0 + a_c);
        }
        #pragma unroll
        for (int i = 0; i < 2; i++)
            br[i] = (bn + b_c < N)
                  ? *(const float4*)(B + (size_t)(k0 + b_r + i * 8) * N + bn + b_c)
                  : make_float4(0.f, 0.f, 0.f, 0.f);
    };

    auto store_chunk = [&](int buf) {
        if (ACOL) {
            #pragma unroll
            for (int i = 0; i < 2; i++) {
                int idx = t + i * 256;
                int k   = idx >> 5;
                int mq  = (idx & 31) * 4;
                uint4 u = make_uint4(f2tf(ar[i].x), f2tf(ar[i].y),
                                     f2tf(ar[i].z), f2tf(ar[i].w));
                *(uint4*)&Ask[buf][k][mq] = u;
            }
        } else {
            #pragma unroll
            for (int i = 0; i < 2; i++) {
                int r = a_r + i * 64;
                As[buf][r][a_c + 0] = f2tf(ar[i].x);
                As[buf][r][a_c + 1] = f2tf(ar[i].y);
                As[buf][r][a_c + 2] = f2tf(ar[i].z);
                As[buf][r][a_c + 3] = f2tf(ar[i].w);
            }
        }
        #pragma unroll
        for (int i = 0; i < 2; i++) {
            int rb = b_r + i * 8;
            Bs[buf][rb][b_c + 0] = f2tf(br[i].x);
            Bs[buf][rb][b_c + 1] = f2tf(br[i].y);
            Bs[buf][rb][b_c + 2] = f2tf(br[i].z);
            Bs[buf][rb][b_c + 3] = f2tf(br[i].w);
        }
    };

    load_chunk(0);
    store_chunk(0);
    __syncthreads();

    for (int kc = 0; kc < nk; kc++) {
        const int cur = kc & 1;
        const int nxt = cur ^ 1;
        if (kc + 1 < nk) load_chunk((kc + 1) << 4);

        #pragma unroll
        for (int ks = 0; ks < 2; ks++) {
            const int k = ks * 8;
            unsigned af[4][4], bf[4][2];
            #pragma unroll
            for (int mi = 0; mi < 4; mi++) {
                int m0 = wm + mi * 16;
                if (ACOL) {
                    af[mi][0] = Ask[cur][k + q    ][m0 + gid];
                    af[mi][1] = Ask[cur][k + q    ][m0 + gid + 8];
                    af[mi][2] = Ask[cur][k + q + 4][m0 + gid];
                    af[mi][3] = Ask[cur][k + q + 4][m0 + gid + 8];
                } else {
                    af[mi][0] = As[cur][m0 + gid    ][k + q];
                    af[mi][1] = As[cur][m0 + gid + 8][k + q];
                    af[mi][2] = As[cur][m0 + gid    ][k + q + 4];
                    af[mi][3] = As[cur][m0 + gid + 8][k + q + 4];
                }
            }
            #pragma unroll
            for (int ni = 0; ni < 4; ni++) {
                int n0 = wn + ni * 8 + gid;
                bf[ni][0] = Bs[cur][k + q    ][n0];
                bf[ni][1] = Bs[cur][k + q + 4][n0];
            }
            #pragma unroll
            for (int mi = 0; mi < 4; mi++)
                #pragma unroll
                for (int ni = 0; ni < 4; ni++) {
                    asm volatile(
                        "mma.sync.aligned.m16n8k8.row.col.f32.tf32.tf32.f32 "
                        "{%0,%1,%2,%3}, {%4,%5,%6,%7}, {%8,%9}, {%0,%1,%2,%3};\n"
                        : "+f"(acc[mi][ni][0]), "+f"(acc[mi][ni][1]),
                          "+f"(acc[mi][ni][2]), "+f"(acc[mi][ni][3])
                        : "r"(af[mi][0]), "r"(af[mi][1]), "r"(af[mi][2]), "r"(af[mi][3]),
                          "r"(bf[ni][0]), "r"(bf[ni][1]));
                }
        }

        if (kc + 1 < nk) {
            store_chunk(nxt);
            __syncthreads();
        }
    }

    if (OTRANS) {
        const int b   = bm >> 12;
        const int h0  = bm & (HW - 1);
        float* outb = C + (size_t)b * N * HW;
        __syncthreads();
        #pragma unroll
        for (int g = 0; g < 4; g++) {
            if ((warp >> 1) == g) {
                #pragma unroll
                for (int mi = 0; mi < 4; mi++)
                    #pragma unroll
                    for (int ni = 0; ni < 4; ni++) {
                        int cl = ni * 8 + 2 * q;
                        int colg = bn + 32 * g + cl;
                        float al0 = alpha[colg], al1 = alpha[colg + 1];
                        float be0 = beta[colg],  be1 = beta[colg + 1];
                        #pragma unroll
                        for (int h = 0; h < 2; h++) {
                            int rl = wm + mi * 16 + gid + h * 8;
                            cbuf[cl    ][rl] = fmaxf(acc[mi][ni][2 * h + 0] * al0 + be0, 0.f);
                            cbuf[cl + 1][rl] = fmaxf(acc[mi][ni][2 * h + 1] * al1 + be1, 0.f);
                        }
                    }
            }
            __syncthreads();
            {
                int cl = t >> 3;
                int r0 = (t & 7) * 16;
                int c  = bn + 32 * g + cl;
                float4* dst = (float4*)(outb + (size_t)c * HW + h0 + r0);
                const float* src = &cbuf[cl][r0];
                #pragma unroll
                for (int j = 0; j < 4; j++)
                    dst[j] = *(const float4*)(src + 4 * j);
            }
            __syncthreads();
        }
    } else {
        #pragma unroll
        for (int mi = 0; mi < 4; mi++) {
            #pragma unroll
            for (int ni = 0; ni < 4; ni++) {
                int col = bn + wn + ni * 8 + 2 * q;
                if (col >= N) continue;
                float al0 = alpha ? alpha[col]     : 1.0f;
                float al1 = alpha ? alpha[col + 1] : 1.0f;
                float be0 = beta  ? beta[col]      : 0.0f;
                float be1 = beta  ? beta[col + 1]  : 0.0f;
                #pragma unroll
                for (int h = 0; h < 2; h++) {
                    int row = bm + wm + mi * 16 + gid + h * 8;
                    float v0 = acc[mi][ni][2 * h + 0] * al0 + be0;
                    float v1 = acc[mi][ni][2 * h + 1] * al1 + be1;
                    if (do_relu) { v0 = fmaxf(v0, 0.f); v1 = fmaxf(v1, 0.f); }
                    *(float2*)(C + (size_t)row * N + col) = make_float2(v0, v1);
                }
            }
        }
    }
}

// ---------------------------------------------------------------------------
// Small prep kernels
// ---------------------------------------------------------------------------
__global__ void transpose_kernel(const float* __restrict__ in, float* __restrict__ out,
                                 int R, int C)
{
    __shared__ float tile[32][33];
    int c0 = blockIdx.x * 32;
    int r0 = blockIdx.y * 32;
    int x = threadIdx.x, y = threadIdx.y;
    #pragma unroll
    for (int j = 0; j < 32; j += 8)
        tile[y + j][x] = in[(size_t)(r0 + y + j) * C + c0 + x];
    __syncthreads();
    #pragma unroll
    for (int j = 0; j < 32; j += 8)
        out[(size_t)(c0 + y + j) * R + r0 + x] = tile[x][y + j];
}

__global__ void prep_bn_kernel(const float* g1, const float* b1, const float* m1, const float* v1,
                               const float* g2, const float* b2, const float* m2, const float* v2)
{
    int i = threadIdx.x + blockIdx.x * blockDim.x;
    if (i < DMODEL) {
        float a = g1[i] * rsqrtf(v1[i] + EPSV);
        g_alpha1[i] = a;
        g_beta1[i]  = b1[i] - m1[i] * a;
    }
    if (i < CIN) {
        float a = g2[i] * rsqrtf(v2[i] + EPSV);
        g_alpha2[i] = a;
        g_beta2[i]  = b2[i] - m2[i] * a;
    }
}

// Concat per-layer Woff (D x 64) + Wattn (D x 32) -> WOA [k][n] (D x 96) + bias
__global__ void concat_woa_kernel(const float* __restrict__ Woff_i, const float* __restrict__ boff_i,
                                  const float* __restrict__ Wattn_i, const float* __restrict__ battn_i)
{
    int i = blockIdx.x * blockDim.x + threadIdx.x;
    if (i < DMODEL * NOA) {
        int k = i / NOA, n = i % NOA;
        g_WOA[i] = (n < 64) ? Woff_i[k * 64 + n] : Wattn_i[k * 32 + (n - 64)];
    }
    if (i < NOA)
        g_bOA[i] = (i < 64) ? boff_i[i] : battn_i[i - 64];
}

// ---------------------------------------------------------------------------
// Deformable sampling with fused per-head softmax.
// msel: OA row mask (HW-1 when OA is batch-broadcast, -1 otherwise)
// ---------------------------------------------------------------------------
__device__ __forceinline__ float fetch_val(const float* __restrict__ vb, int xi, int yi, int c)
{
    if (xi < 0 || xi >= WW || yi < 0 || yi >= HH) return 0.0f;
    return vb[((size_t)(yi * WW + xi)) * DMODEL + c];
}

__global__ void __launch_bounds__(256)
deform_sample_kernel(const float* __restrict__ VAL, const float* __restrict__ OA,
                     float* __restrict__ O, int msel)
{
    int m = blockIdx.x;
    int b = m >> 12;
    int pix = m & (HW - 1);
    int t = threadIdx.x;
    int head = t >> 5;
    int c = t;

    float rx = ((pix & (WW - 1)) + 0.5f) * (1.0f / WW);
    float ry = ((pix >> 6) + 0.5f) * (1.0f / HH);

    int idx = m & msel;
    const float* vb   = VAL + (size_t)b * HW * DMODEL;
    const float* offm = OA + (size_t)idx * NOA + head * (NP * 2);
    const float* lg   = OA + (size_t)idx * NOA + 64 + head * NP;

    float l0 = lg[0], l1 = lg[1], l2 = lg[2], l3 = lg[3];
    float mx = fmaxf(fmaxf(l0, l1), fmaxf(l2, l3));
    float e0 = __expf(l0 - mx), e1 = __expf(l1 - mx);
    float e2 = __expf(l2 - mx), e3 = __expf(l3 - mx);
    float inv = 1.0f / (e0 + e1 + e2 + e3);
    float w[4] = { e0 * inv, e1 * inv, e2 * inv, e3 * inv };

    float acc = 0.0f;
    #pragma unroll
    for (int p = 0; p < NP; p++) {
        float lx = rx + offm[p * 2 + 0] * (1.0f / WW);
        float ly = ry + offm[p * 2 + 1] * (1.0f / HH);
        float gx = lx * WW - 0.5f;
        float gy = ly * HH - 0.5f;
        float fx = floorf(gx), fy = floorf(gy);
        int x0 = (int)fx, y0 = (int)fy;
        float wx = gx - fx, wy = gy - fy;
        float v00 = fetch_val(vb, x0,     y0,     c);
        float v10 = fetch_val(vb, x0 + 1, y0,     c);
        float v01 = fetch_val(vb, x0,     y0 + 1, c);
        float v11 = fetch_val(vb, x0 + 1, y0 + 1, c);
        float s = v00 * (1.f - wx) * (1.f - wy) + v10 * wx * (1.f - wy)
                + v01 * (1.f - wx) * wy         + v11 * wx * wy;
        acc = fmaf(w[p], s, acc);
    }
    O[(size_t)m * DMODEL + c] = acc;
}

// ---------------------------------------------------------------------------
// Residual + LayerNorm: Q[m] = LN(S[m & smask] + T[m]).
// S may be qembed (batch-broadcast, smask=HW-1) or Q itself (smask=-1).
// ---------------------------------------------------------------------------
__global__ void __launch_bounds__(256)
resid_ln_kernel(const float* __restrict__ S, int smask,
                float* __restrict__ Q, const float* __restrict__ T,
                const float* __restrict__ gamma, const float* __restrict__ beta)
{
    int row  = blockIdx.x * 8 + (threadIdx.x >> 5);
    int lane = threadIdx.x & 31;
    int srow = row & smask;
    const float4* qr = (const float4*)(S + (size_t)srow * DMODEL);
    const float4* tr = (const float4*)(T + (size_t)row * DMODEL);

    float x[8];
    float sum = 0.f, sumsq = 0.f;
    #pragma unroll
    for (int i = 0; i < 2; i++) {
        float4 a = qr[lane + i * 32];
        float4 b = tr[lane + i * 32];
        float v0 = a.x + b.x, v1 = a.y + b.y, v2 = a.z + b.z, v3 = a.w + b.w;
        x[i * 4 + 0] = v0; x[i * 4 + 1] = v1; x[i * 4 + 2] = v2; x[i * 4 + 3] = v3;
        sum += v0 + v1 + v2 + v3;
        sumsq += v0 * v0 + v1 * v1 + v2 * v2 + v3 * v3;
    }
    #pragma unroll
    for (int s = 16; s > 0; s >>= 1) {
        sum   += __shfl_xor_sync(0xffffffffu, sum, s);
        sumsq += __shfl_xor_sync(0xffffffffu, sumsq, s);
    }
    float mean = sum * (1.0f / DMODEL);
    float var  = sumsq * (1.0f / DMODEL) - mean * mean;
    float rstd = rsqrtf(var + EPSV);

    float4* qw = (float4*)(Q + (size_t)row * DMODEL);
    #pragma unroll
    for (int i = 0; i < 2; i++) {
        int e = (lane + i * 32) * 4;
        float4 o;
        o.x = (x[i * 4 + 0] - mean) * rstd * gamma[e + 0] + beta[e + 0];
        o.y = (x[i * 4 + 1] - mean) * rstd * gamma[e + 1] + beta[e + 1];
        o.z = (x[i * 4 + 2] - mean) * rstd * gamma[e + 2] + beta[e + 2];
        o.w = (x[i * 4 + 3] - mean) * rstd * gamma[e + 3] + beta[e + 3];
        qw[lane + i * 32] = o;
    }
}

// ---------------------------------------------------------------------------
// Launch
// ---------------------------------------------------------------------------
extern "C" void kernel_launch(void* const* d_in, const int* in_sizes, int n_in,
                              void* d_out, int out_size)
{
    const float* x      = (const float*)d_in[0];
    const float* W_in   = (const float*)d_in[1];
    const float* bn1_g  = (const float*)d_in[2];
    const float* bn1_b  = (const float*)d_in[3];
    const float* bn1_m  = (const float*)d_in[4];
    const float* bn1_v  = (const float*)d_in[5];
    const float* qembed = (const float*)d_in[6];
    const float* Woff   = (const float*)d_in[7];
    const float* boff   = (const float*)d_in[8];
    const float* Wattn  = (const float*)d_in[9];
    const float* battn  = (const float*)d_in[10];
    const float* Wval   = (const float*)d_in[11];
    const float* bval   = (const float*)d_in[12];
    const float* Wo     = (const float*)d_in[13];
    const float* bo     = (const float*)d_in[14];
    const float* ln1_g  = (const float*)d_in[15];
    const float* ln1_b  = (const float*)d_in[16];
    const float* W1     = (const float*)d_in[17];
    const float* b1     = (const float*)d_in[18];
    const float* W2     = (const float*)d_in[19];
    const float* b2     = (const float*)d_in[20];
    const float* ln2_g  = (const float*)d_in[21];
    const float* ln2_b  = (const float*)d_in[22];
    const float* W_out  = (const float*)d_in[23];
    const float* bn2_g  = (const float*)d_in[24];
    const float* bn2_b  = (const float*)d_in[25];
    const float* bn2_m  = (const float*)d_in[26];
    const float* bn2_v  = (const float*)d_in[27];
    float* out = (float*)d_out;

    float *SRC, *Q, *VAL, *T1, *OA, *H, *WIT, *WOT, *WOA, *bOA;
    float *al1, *be1, *al2, *be2;
    cudaGetSymbolAddress((void**)&SRC, g_SRC);
    cudaGetSymbolAddress((void**)&Q,   g_Q);
    cudaGetSymbolAddress((void**)&VAL, g_VAL);
    cudaGetSymbolAddress((void**)&T1,  g_T1);
    cudaGetSymbolAddress((void**)&OA,  g_OA);
    cudaGetSymbolAddress((void**)&H,   g_H);
    cudaGetSymbolAddress((void**)&WIT, g_WIT);
    cudaGetSymbolAddress((void**)&WOT, g_WOT);
    cudaGetSymbolAddress((void**)&WOA, g_WOA);
    cudaGetSymbolAddress((void**)&bOA, g_bOA);
    cudaGetSymbolAddress((void**)&al1, g_alpha1);
    cudaGetSymbolAddress((void**)&be1, g_beta1);
    cudaGetSymbolAddress((void**)&al2, g_alpha2);
    cudaGetSymbolAddress((void**)&be2, g_beta2);

    dim3 tb32(32, 8);

    // launches 0..2, then launch index 3 = proj_in GEMM (ncu capture target)
    prep_bn_kernel<<<1, 512>>>(bn1_g, bn1_b, bn1_m, bn1_v, bn2_g, bn2_b, bn2_m, bn2_v);
    transpose_kernel<<<dim3(CIN / 32, DMODEL / 32), tb32>>>(W_in, WIT, DMODEL, CIN);
    concat_woa_kernel<<<(DMODEL * NOA + 255) / 256, 256>>>(Woff, boff, Wattn, battn);

    // proj_in: A = x directly (ACOL), B = W_in^T, fused BN+ReLU epilogue
    gemm_tf32_kernel<1, 0><<<dim3(DMODEL / 128, MROWS / 128), 256>>>(
        x, WIT, SRC, MROWS, DMODEL, CIN, al1, be1, 1);

    transpose_kernel<<<dim3(DMODEL / 32, CIN / 32), tb32>>>(W_out, WOT, CIN, DMODEL);

    for (int i = 0; i < LNUM; i++) {
        const float* Wval_i  = Wval  + (size_t)i * DMODEL * DMODEL;
        const float* bval_i  = bval  + (size_t)i * DMODEL;
        const float* Woff_i  = Woff  + (size_t)i * DMODEL * (NH * NP * 2);
        const float* boff_i  = boff  + (size_t)i * (NH * NP * 2);
        const float* Wattn_i = Wattn + (size_t)i * DMODEL * (NH * NP);
        const float* battn_i = battn + (size_t)i * (NH * NP);
        const float* Wo_i    = Wo    + (size_t)i * DMODEL * DMODEL;
        const float* bo_i    = bo    + (size_t)i * DMODEL;
        const float* W1_i    = W1    + (size_t)i * DMODEL * DFF;
        const float* b1_i    = b1    + (size_t)i * DFF;
        const float* W2_i    = W2    + (size_t)i * DFF * DMODEL;
        const float* b2_i    = b2    + (size_t)i * DMODEL;

        if (i > 0)
            concat_woa_kernel<<<(DMODEL * NOA + 255) / 256, 256>>>(Woff_i, boff_i,
                                                                   Wattn_i, battn_i);

        gemm_tf32_kernel<0, 0><<<dim3(DMODEL / 128, MROWS / 128), 256>>>(
            SRC, Wval_i, VAL, MROWS, DMODEL, DMODEL, nullptr, bval_i, 0);

        // offsets + attn logits. Layer 0: Q == broadcast(qembed) -> compute
        // only HW rows directly from qembed; sampler indexes OA by pixel.
        const float* qsrc = (i == 0) ? qembed : Q;
        int oam  = (i == 0) ? HW : MROWS;
        int msel = (i == 0) ? (HW - 1) : -1;
        gemm_tf32_kernel<0, 0><<<dim3(1, oam / 128), 256>>>(
            qsrc, WOA, OA, oam, NOA, DMODEL, nullptr, bOA, 0);

        deform_sample_kernel<<<MROWS, 256>>>(VAL, OA, H, msel);

        gemm_tf32_kernel<0, 0><<<dim3(DMODEL / 128, MROWS / 128), 256>>>(
            H, Wo_i, T1, MROWS, DMODEL, DMODEL, nullptr, bo_i, 0);
        // layer 0 ln1 residual source is qembed (broadcast); writes full Q
        resid_ln_kernel<<<MROWS / 8, 256>>>(qsrc, msel, Q, T1,
                                            ln1_g + (size_t)i * DMODEL,
                                            ln1_b + (size_t)i * DMODEL);
        gemm_tf32_kernel<0, 0><<<dim3(DFF / 128, MROWS / 128), 256>>>(
            Q, W1_i, H, MROWS, DFF, DMODEL, nullptr, b1_i, 1);
        gemm_tf32_kernel<0, 0><<<dim3(DMODEL / 128, MROWS / 128), 256>>>(
            H, W2_i, T1, MROWS, DMODEL, DFF, nullptr, b2_i, 0);
        resid_ln_kernel<<<MROWS / 8, 256>>>(Q, -1, Q, T1,
                                            ln2_g + (size_t)i * DMODEL,
                                            ln2_b + (size_t)i * DMODEL);
    }

    // proj_out: fused BN+ReLU+transpose epilogue writes out[b][c][hw]
    gemm_tf32_kernel<0, 1><<<dim3(CIN / 128, MROWS / 128), 256>>>(
        Q, WOT, out, MROWS, CIN, DMODEL, al2, be2, 1);
}

// round 15
// speedup vs baseline: 1.5461x; 1.5461x over previous
#include <cuda_runtime.h>
#include <cuda_bf16.h>
#include <cuda_fp16.h>
#include <cstdint>
#include <math.h>

// ---------------------------------------------------------------------------
// Problem constants
// ---------------------------------------------------------------------------
#define LNUM 2
#define DMODEL 256
#define DFF 1024
#define NH 8
#define NP 4
#define CIN 512
#define BATCH 8
#define HH 64
#define WW 64
#define HW (HH * WW)            // 4096
#define MROWS (BATCH * HW)      // 32768
#define EPSV 1e-5f
#define NOA 96                  // merged offsets(64)+attn(32)

// ---------------------------------------------------------------------------
// Scratch (device globals; no dynamic allocation allowed)
// ---------------------------------------------------------------------------
__device__ float g_SRC[(size_t)MROWS * DMODEL];
__device__ float g_Q[(size_t)MROWS * DMODEL];
__device__ float g_VAL[(size_t)MROWS * DMODEL];  // used as __half when OHALF
__device__ float g_T1[(size_t)MROWS * DMODEL];
__device__ float g_OA[(size_t)MROWS * NOA];
__device__ float g_H[(size_t)MROWS * DFF];
__device__ float g_WIT[CIN * DMODEL];    // W_in^T  [CIN][D]
__device__ float g_WOT[DMODEL * CIN];    // W_out^T [D][CIN]
__device__ float g_WOA[DMODEL * NOA];    // [k][n]
__device__ float g_bOA[NOA];
__device__ float g_alpha1[DMODEL], g_beta1[DMODEL];
__device__ float g_alpha2[CIN],    g_beta2[CIN];

// ---------------------------------------------------------------------------
// tf32 conversion (round-to-nearest)
// ---------------------------------------------------------------------------
__device__ __forceinline__ unsigned f2tf(float f)
{
    unsigned r;
    asm("cvt.rna.tf32.f32 %0, %1;" : "=r"(r) : "f"(f));
    return r;
}

// ---------------------------------------------------------------------------
// TF32 tensor-core GEMM, double-buffered smem (R12-proven core, no occ cap).
//   C[M,N] = act((A[M,K] @ B[K,N]) * alpha[n] + beta[n])
// Block tile 128x128, BK=16, 8 warps (warp tile 64x32), mma.m16n8k8.
// ACOL=1:  A is x-layout [b][k][hw]; staged as [k][m] (tile within one batch).
// OTRANS=1: epilogue restages via smem, writes out[b][c][hw] + BN+ReLU.
// OHALF=1: C is __half [m][N] (aligned half2 stores).
// ---------------------------------------------------------------------------
template<int ACOL, int OTRANS, int OHALF>
__global__ void __launch_bounds__(256)
gemm_tf32_kernel(const float* __restrict__ A, const float* __restrict__ B,
                 void* __restrict__ Cv, int M, int N, int K,
                 const float* __restrict__ alpha, const float* __restrict__ beta,
                 int do_relu)
{
    // raw smem, aliased three ways
    __shared__ __align__(16) unsigned sraw[2 * 128 * 20 + 2 * 16 * 136];
    unsigned (*As)[128][20]  = (unsigned(*)[128][20])sraw;              // AROW
    unsigned (*Ask)[16][136] = (unsigned(*)[16][136])sraw;              // ACOL
    unsigned (*Bs)[16][136]  = (unsigned(*)[16][136])(sraw + 2 * 128 * 20);
    float    (*cbuf)[132]    = (float(*)[132])sraw;                     // OTRANS epi

    const int t    = threadIdx.x;
    const int bm   = blockIdx.y * 128;
    const int bn   = blockIdx.x * 128;
    const int warp = t >> 5;
    const int lane = t & 31;
    const int wm   = (warp & 1) * 64;
    const int wn   = (warp >> 1) * 32;
    const int gid  = lane >> 2;
    const int q    = lane & 3;

    const int a_r = t >> 2;
    const int a_c = (t & 3) * 4;
    const int b_r = t >> 5;
    const int b_c = (t & 31) * 4;

    const float* Axb = A;
    int hw0 = 0;
    if (ACOL) {
        int batch = bm >> 12;
        hw0 = bm & (HW - 1);
        Axb = A + (size_t)batch * K * HW;
    }

    float4 ar[2], br[2];

    float acc[4][4][4];
    #pragma unroll
    for (int mi = 0; mi < 4; mi++)
        #pragma unroll
        for (int ni = 0; ni < 4; ni++)
            #pragma unroll
            for (int r = 0; r < 4; r++) acc[mi][ni][r] = 0.0f;

    const int nk = K >> 4;

    auto load_chunk = [&](int k0) {
        if (ACOL) {
            #pragma unroll
            for (int i = 0; i < 2; i++) {
                int idx = t + i * 256;
                int k   = idx >> 5;
                int mq  = (idx & 31) * 4;
                ar[i] = *(const float4*)(Axb + (size_t)(k0 + k) * HW + hw0 + mq);
            }
        } else {
            #pragma unroll
            for (int i = 0; i < 2; i++)
                ar[i] = *(const float4*)(A + (size_t)(bm + a_r + i * 64) * K + k0 + a_c);
        }
        #pragma unroll
        for (int i = 0; i < 2; i++)
            br[i] = (bn + b_c < N)
                  ? *(const float4*)(B + (size_t)(k0 + b_r + i * 8) * N + bn + b_c)
                  : make_float4(0.f, 0.f, 0.f, 0.f);
    };

    auto store_chunk = [&](int buf) {
        if (ACOL) {
            #pragma unroll
            for (int i = 0; i < 2; i++) {
                int idx = t + i * 256;
                int k   = idx >> 5;
                int mq  = (idx & 31) * 4;
                uint4 u = make_uint4(f2tf(ar[i].x), f2tf(ar[i].y),
                                     f2tf(ar[i].z), f2tf(ar[i].w));
                *(uint4*)&Ask[buf][k][mq] = u;
            }
        } else {
            #pragma unroll
            for (int i = 0; i < 2; i++) {
                int r = a_r + i * 64;
                As[buf][r][a_c + 0] = f2tf(ar[i].x);
                As[buf][r][a_c + 1] = f2tf(ar[i].y);
                As[buf][r][a_c + 2] = f2tf(ar[i].z);
                As[buf][r][a_c + 3] = f2tf(ar[i].w);
            }
        }
        #pragma unroll
        for (int i = 0; i < 2; i++) {
            int rb = b_r + i * 8;
            Bs[buf][rb][b_c + 0] = f2tf(br[i].x);
            Bs[buf][rb][b_c + 1] = f2tf(br[i].y);
            Bs[buf][rb][b_c + 2] = f2tf(br[i].z);
            Bs[buf][rb][b_c + 3] = f2tf(br[i].w);
        }
    };

    load_chunk(0);
    store_chunk(0);
    __syncthreads();

    for (int kc = 0; kc < nk; kc++) {
        const int cur = kc & 1;
        const int nxt = cur ^ 1;
        if (kc + 1 < nk) load_chunk((kc + 1) << 4);

        #pragma unroll
        for (int ks = 0; ks < 2; ks++) {
            const int k = ks * 8;
            unsigned af[4][4], bf[4][2];
            #pragma unroll
            for (int mi = 0; mi < 4; mi++) {
                int m0 = wm + mi * 16;
                if (ACOL) {
                    af[mi][0] = Ask[cur][k + q    ][m0 + gid];
                    af[mi][1] = Ask[cur][k + q    ][m0 + gid + 8];
                    af[mi][2] = Ask[cur][k + q + 4][m0 + gid];
                    af[mi][3] = Ask[cur][k + q + 4][m0 + gid + 8];
                } else {
                    af[mi][0] = As[cur][m0 + gid    ][k + q];
                    af[mi][1] = As[cur][m0 + gid + 8][k + q];
                    af[mi][2] = As[cur][m0 + gid    ][k + q + 4];
                    af[mi][3] = As[cur][m0 + gid + 8][k + q + 4];
                }
            }
            #pragma unroll
            for (int ni = 0; ni < 4; ni++) {
                int n0 = wn + ni * 8 + gid;
                bf[ni][0] = Bs[cur][k + q    ][n0];
                bf[ni][1] = Bs[cur][k + q + 4][n0];
            }
            #pragma unroll
            for (int mi = 0; mi < 4; mi++)
                #pragma unroll
                for (int ni = 0; ni < 4; ni++) {
                    asm volatile(
                        "mma.sync.aligned.m16n8k8.row.col.f32.tf32.tf32.f32 "
                        "{%0,%1,%2,%3}, {%4,%5,%6,%7}, {%8,%9}, {%0,%1,%2,%3};\n"
                        : "+f"(acc[mi][ni][0]), "+f"(acc[mi][ni][1]),
                          "+f"(acc[mi][ni][2]), "+f"(acc[mi][ni][3])
                        : "r"(af[mi][0]), "r"(af[mi][1]), "r"(af[mi][2]), "r"(af[mi][3]),
                          "r"(bf[ni][0]), "r"(bf[ni][1]));
                }
        }

        if (kc + 1 < nk) {
            store_chunk(nxt);
            __syncthreads();
        }
    }

    if (OTRANS) {
        const int b   = bm >> 12;
        const int h0  = bm & (HW - 1);
        float* outb = (float*)Cv + (size_t)b * N * HW;
        __syncthreads();
        #pragma unroll
        for (int g = 0; g < 4; g++) {
            if ((warp >> 1) == g) {
                #pragma unroll
                for (int mi = 0; mi < 4; mi++)
                    #pragma unroll
                    for (int ni = 0; ni < 4; ni++) {
                        int cl = ni * 8 + 2 * q;
                        int colg = bn + 32 * g + cl;
                        float al0 = alpha[colg], al1 = alpha[colg + 1];
                        float be0 = beta[colg],  be1 = beta[colg + 1];
                        #pragma unroll
                        for (int h = 0; h < 2; h++) {
                            int rl = wm + mi * 16 + gid + h * 8;
                            cbuf[cl    ][rl] = fmaxf(acc[mi][ni][2 * h + 0] * al0 + be0, 0.f);
                            cbuf[cl + 1][rl] = fmaxf(acc[mi][ni][2 * h + 1] * al1 + be1, 0.f);
                        }
                    }
            }
            __syncthreads();
            {
                int cl = t >> 3;
                int r0 = (t & 7) * 16;
                int c  = bn + 32 * g + cl;
                float4* dst = (float4*)(outb + (size_t)c * HW + h0 + r0);
                const float* src = &cbuf[cl][r0];
                #pragma unroll
                for (int j = 0; j < 4; j++)
                    dst[j] = *(const float4*)(src + 4 * j);
            }
            __syncthreads();
        }
    } else {
        #pragma unroll
        for (int mi = 0; mi < 4; mi++) {
            #pragma unroll
            for (int ni = 0; ni < 4; ni++) {
                int col = bn + wn + ni * 8 + 2 * q;
                if (col >= N) continue;
                float al0 = alpha ? alpha[col]     : 1.0f;
                float al1 = alpha ? alpha[col + 1] : 1.0f;
                float be0 = beta  ? beta[col]      : 0.0f;
                float be1 = beta  ? beta[col + 1]  : 0.0f;
                #pragma unroll
                for (int h = 0; h < 2; h++) {
                    int row = bm + wm + mi * 16 + gid + h * 8;
                    float v0 = acc[mi][ni][2 * h + 0] * al0 + be0;
                    float v1 = acc[mi][ni][2 * h + 1] * al1 + be1;
                    if (do_relu) { v0 = fmaxf(v0, 0.f); v1 = fmaxf(v1, 0.f); }
                    if (OHALF) {
                        __half2* Ch = (__half2*)Cv;
                        Ch[((size_t)row * N + col) >> 1] = __floats2half2_rn(v0, v1);
                    } else {
                        *(float2*)((float*)Cv + (size_t)row * N + col) = make_float2(v0, v1);
                    }
                }
            }
        }
    }
}

// ---------------------------------------------------------------------------
// Small prep kernels
// ---------------------------------------------------------------------------
__global__ void transpose_kernel(const float* __restrict__ in, float* __restrict__ out,
                                 int R, int C)
{
    __shared__ float tile[32][33];
    int c0 = blockIdx.x * 32;
    int r0 = blockIdx.y * 32;
    int x = threadIdx.x, y = threadIdx.y;
    #pragma unroll
    for (int j = 0; j < 32; j += 8)
        tile[y + j][x] = in[(size_t)(r0 + y + j) * C + c0 + x];
    __syncthreads();
    #pragma unroll
    for (int j = 0; j < 32; j += 8)
        out[(size_t)(c0 + y + j) * R + r0 + x] = tile[x][y + j];
}

__global__ void prep_bn_kernel(const float* g1, const float* b1, const float* m1, const float* v1,
                               const float* g2, const float* b2, const float* m2, const float* v2)
{
    int i = threadIdx.x + blockIdx.x * blockDim.x;
    if (i < DMODEL) {
        float a = g1[i] * rsqrtf(v1[i] + EPSV);
        g_alpha1[i] = a;
        g_beta1[i]  = b1[i] - m1[i] * a;
    }
    if (i < CIN) {
        float a = g2[i] * rsqrtf(v2[i] + EPSV);
        g_alpha2[i] = a;
        g_beta2[i]  = b2[i] - m2[i] * a;
    }
}

// Concat per-layer Woff (D x 64) + Wattn (D x 32) -> WOA [k][n] (D x 96) + bias
__global__ void concat_woa_kernel(const float* __restrict__ Woff_i, const float* __restrict__ boff_i,
                                  const float* __restrict__ Wattn_i, const float* __restrict__ battn_i)
{
    int i = blockIdx.x * blockDim.x + threadIdx.x;
    if (i < DMODEL * NOA) {
        int k = i / NOA, n = i % NOA;
        g_WOA[i] = (n < 64) ? Woff_i[k * 64 + n] : Wattn_i[k * 32 + (n - 64)];
    }
    if (i < NOA)
        g_bOA[i] = (i < 64) ? boff_i[i] : battn_i[i - 64];
}

// ---------------------------------------------------------------------------
// Deformable sampling with fused per-head softmax. VAL is fp16.
// msel: OA row mask (HW-1 when OA is batch-broadcast, -1 otherwise)
// ---------------------------------------------------------------------------
__device__ __forceinline__ float fetch_valh(const __half* __restrict__ vb, int xi, int yi, int c)
{
    if (xi < 0 || xi >= WW || yi < 0 || yi >= HH) return 0.0f;
    return __half2float(vb[((size_t)(yi * WW + xi)) * DMODEL + c]);
}

__global__ void __launch_bounds__(256)
deform_sample_kernel(const __half* __restrict__ VAL, const float* __restrict__ OA,
                     float* __restrict__ O, int msel)
{
    int m = blockIdx.x;
    int b = m >> 12;
    int pix = m & (HW - 1);
    int t = threadIdx.x;
    int head = t >> 5;
    int c = t;

    float rx = ((pix & (WW - 1)) + 0.5f) * (1.0f / WW);
    float ry = ((pix >> 6) + 0.5f) * (1.0f / HH);

    int idx = m & msel;
    const __half* vb  = VAL + (size_t)b * HW * DMODEL;
    const float* offm = OA + (size_t)idx * NOA + head * (NP * 2);
    const float* lg   = OA + (size_t)idx * NOA + 64 + head * NP;

    float l0 = lg[0], l1 = lg[1], l2 = lg[2], l3 = lg[3];
    float mx = fmaxf(fmaxf(l0, l1), fmaxf(l2, l3));
    float e0 = __expf(l0 - mx), e1 = __expf(l1 - mx);
    float e2 = __expf(l2 - mx), e3 = __expf(l3 - mx);
    float inv = 1.0f / (e0 + e1 + e2 + e3);
    float w[4] = { e0 * inv, e1 * inv, e2 * inv, e3 * inv };

    float acc = 0.0f;
    #pragma unroll
    for (int p = 0; p < NP; p++) {
        float lx = rx + offm[p * 2 + 0] * (1.0f / WW);
        float ly = ry + offm[p * 2 + 1] * (1.0f / HH);
        float gx = lx * WW - 0.5f;
        float gy = ly * HH - 0.5f;
        float fx = floorf(gx), fy = floorf(gy);
        int x0 = (int)fx, y0 = (int)fy;
        float wx = gx - fx, wy = gy - fy;
        float v00 = fetch_valh(vb, x0,     y0,     c);
        float v10 = fetch_valh(vb, x0 + 1, y0,     c);
        float v01 = fetch_valh(vb, x0,     y0 + 1, c);
        float v11 = fetch_valh(vb, x0 + 1, y0 + 1, c);
        float s = v00 * (1.f - wx) * (1.f - wy) + v10 * wx * (1.f - wy)
                + v01 * (1.f - wx) * wy         + v11 * wx * wy;
        acc = fmaf(w[p], s, acc);
    }
    O[(size_t)m * DMODEL + c] = acc;
}

// ---------------------------------------------------------------------------
// Residual + LayerNorm: Q[m] = LN(S[m & smask] + T[m]).
// ---------------------------------------------------------------------------
__global__ void __launch_bounds__(256)
resid_ln_kernel(const float* __restrict__ S, int smask,
                float* __restrict__ Q, const float* __restrict__ T,
                const float* __restrict__ gamma, const float* __restrict__ beta)
{
    int row  = blockIdx.x * 8 + (threadIdx.x >> 5);
    int lane = threadIdx.x & 31;
    int srow = row & smask;
    const float4* qr = (const float4*)(S + (size_t)srow * DMODEL);
    const float4* tr = (const float4*)(T + (size_t)row * DMODEL);

    float x[8];
    float sum = 0.f, sumsq = 0.f;
    #pragma unroll
    for (int i = 0; i < 2; i++) {
        float4 a = qr[lane + i * 32];
        float4 b = tr[lane + i * 32];
        float v0 = a.x + b.x, v1 = a.y + b.y, v2 = a.z + b.z, v3 = a.w + b.w;
        x[i * 4 + 0] = v0; x[i * 4 + 1] = v1; x[i * 4 + 2] = v2; x[i * 4 + 3] = v3;
        sum += v0 + v1 + v2 + v3;
        sumsq += v0 * v0 + v1 * v1 + v2 * v2 + v3 * v3;
    }
    #pragma unroll
    for (int s = 16; s > 0; s >>= 1) {
        sum   += __shfl_xor_sync(0xffffffffu, sum, s);
        sumsq += __shfl_xor_sync(0xffffffffu, sumsq, s);
    }
    float mean = sum * (1.0f / DMODEL);
    float var  = sumsq * (1.0f / DMODEL) - mean * mean;
    float rstd = rsqrtf(var + EPSV);

    float4* qw = (float4*)(Q + (size_t)row * DMODEL);
    #pragma unroll
    for (int i = 0; i < 2; i++) {
        int e = (lane + i * 32) * 4;
        float4 o;
        o.x = (x[i * 4 + 0] - mean) * rstd * gamma[e + 0] + beta[e + 0];
        o.y = (x[i * 4 + 1] - mean) * rstd * gamma[e + 1] + beta[e + 1];
        o.z = (x[i * 4 + 2] - mean) * rstd * gamma[e + 2] + beta[e + 2];
        o.w = (x[i * 4 + 3] - mean) * rstd * gamma[e + 3] + beta[e + 3];
        qw[lane + i * 32] = o;
    }
}

// ---------------------------------------------------------------------------
// Launch
// ---------------------------------------------------------------------------
extern "C" void kernel_launch(void* const* d_in, const int* in_sizes, int n_in,
                              void* d_out, int out_size)
{
    const float* x      = (const float*)d_in[0];
    const float* W_in   = (const float*)d_in[1];
    const float* bn1_g  = (const float*)d_in[2];
    const float* bn1_b  = (const float*)d_in[3];
    const float* bn1_m  = (const float*)d_in[4];
    const float* bn1_v  = (const float*)d_in[5];
    const float* qembed = (const float*)d_in[6];
    const float* Woff   = (const float*)d_in[7];
    const float* boff   = (const float*)d_in[8];
    const float* Wattn  = (const float*)d_in[9];
    const float* battn  = (const float*)d_in[10];
    const float* Wval   = (const float*)d_in[11];
    const float* bval   = (const float*)d_in[12];
    const float* Wo     = (const float*)d_in[13];
    const float* bo     = (const float*)d_in[14];
    const float* ln1_g  = (const float*)d_in[15];
    const float* ln1_b  = (const float*)d_in[16];
    const float* W1     = (const float*)d_in[17];
    const float* b1     = (const float*)d_in[18];
    const float* W2     = (const float*)d_in[19];
    const float* b2     = (const float*)d_in[20];
    const float* ln2_g  = (const float*)d_in[21];
    const float* ln2_b  = (const float*)d_in[22];
    const float* W_out  = (const float*)d_in[23];
    const float* bn2_g  = (const float*)d_in[24];
    const float* bn2_b  = (const float*)d_in[25];
    const float* bn2_m  = (const float*)d_in[26];
    const float* bn2_v  = (const float*)d_in[27];
    float* out = (float*)d_out;

    float *SRC, *Q, *VAL, *T1, *OA, *H, *WIT, *WOT, *WOA, *bOA;
    float *al1, *be1, *al2, *be2;
    cudaGetSymbolAddress((void**)&SRC, g_SRC);
    cudaGetSymbolAddress((void**)&Q,   g_Q);
    cudaGetSymbolAddress((void**)&VAL, g_VAL);
    cudaGetSymbolAddress((void**)&T1,  g_T1);
    cudaGetSymbolAddress((void**)&OA,  g_OA);
    cudaGetSymbolAddress((void**)&H,   g_H);
    cudaGetSymbolAddress((void**)&WIT, g_WIT);
    cudaGetSymbolAddress((void**)&WOT, g_WOT);
    cudaGetSymbolAddress((void**)&WOA, g_WOA);
    cudaGetSymbolAddress((void**)&bOA, g_bOA);
    cudaGetSymbolAddress((void**)&al1, g_alpha1);
    cudaGetSymbolAddress((void**)&be1, g_beta1);
    cudaGetSymbolAddress((void**)&al2, g_alpha2);
    cudaGetSymbolAddress((void**)&be2, g_beta2);

    __half* VALh = (__half*)VAL;

    dim3 tb32(32, 8);

    // launches 0..2, then launch index 3 = proj_in GEMM (ncu capture target)
    prep_bn_kernel<<<1, 512>>>(bn1_g, bn1_b, bn1_m, bn1_v, bn2_g, bn2_b, bn2_m, bn2_v);
    transpose_kernel<<<dim3(CIN / 32, DMODEL / 32), tb32>>>(W_in, WIT, DMODEL, CIN);
    concat_woa_kernel<<<(DMODEL * NOA + 255) / 256, 256>>>(Woff, boff, Wattn, battn);

    // proj_in: A = x directly (ACOL), B = W_in^T, fused BN+ReLU epilogue
    gemm_tf32_kernel<1, 0, 0><<<dim3(DMODEL / 128, MROWS / 128), 256>>>(
        x, WIT, SRC, MROWS, DMODEL, CIN, al1, be1, 1);

    transpose_kernel<<<dim3(DMODEL / 32, CIN / 32), tb32>>>(W_out, WOT, CIN, DMODEL);

    for (int i = 0; i < LNUM; i++) {
        const float* Wval_i  = Wval  + (size_t)i * DMODEL * DMODEL;
        const float* bval_i  = bval  + (size_t)i * DMODEL;
        const float* Woff_i  = Woff  + (size_t)i * DMODEL * (NH * NP * 2);
        const float* boff_i  = boff  + (size_t)i * (NH * NP * 2);
        const float* Wattn_i = Wattn + (size_t)i * DMODEL * (NH * NP);
        const float* battn_i = battn + (size_t)i * (NH * NP);
        const float* Wo_i    = Wo    + (size_t)i * DMODEL * DMODEL;
        const float* bo_i    = bo    + (size_t)i * DMODEL;
        const float* W1_i    = W1    + (size_t)i * DMODEL * DFF;
        const float* b1_i    = b1    + (size_t)i * DFF;
        const float* W2_i    = W2    + (size_t)i * DFF * DMODEL;
        const float* b2_i    = b2    + (size_t)i * DMODEL;

        if (i > 0)
            concat_woa_kernel<<<(DMODEL * NOA + 255) / 256, 256>>>(Woff_i, boff_i,
                                                                   Wattn_i, battn_i);

        // value projection -> fp16 VAL
        gemm_tf32_kernel<0, 0, 1><<<dim3(DMODEL / 128, MROWS / 128), 256>>>(
            SRC, Wval_i, VALh, MROWS, DMODEL, DMODEL, nullptr, bval_i, 0);

        // offsets + attn logits. Layer 0: Q == broadcast(qembed) -> compute
        // only HW rows directly from qembed; sampler indexes OA by pixel.
        const float* qsrc = (i == 0) ? qembed : Q;
        int oam  = (i == 0) ? HW : MROWS;
        int msel = (i == 0) ? (HW - 1) : -1;
        gemm_tf32_kernel<0, 0, 0><<<dim3(1, oam / 128), 256>>>(
            qsrc, WOA, OA, oam, NOA, DMODEL, nullptr, bOA, 0);

        deform_sample_kernel<<<MROWS, 256>>>(VALh, OA, H, msel);

        gemm_tf32_kernel<0, 0, 0><<<dim3(DMODEL / 128, MROWS / 128), 256>>>(
            H, Wo_i, T1, MROWS, DMODEL, DMODEL, nullptr, bo_i, 0);
        // layer 0 ln1 residual source is qembed (broadcast); writes full Q
        resid_ln_kernel<<<MROWS / 8, 256>>>(qsrc, msel, Q, T1,
                                            ln1_g + (size_t)i * DMODEL,
                                            ln1_b + (size_t)i * DMODEL);
        gemm_tf32_kernel<0, 0, 0><<<dim3(DFF / 128, MROWS / 128), 256>>>(
            Q, W1_i, H, MROWS, DFF, DMODEL, nullptr, b1_i, 1);
        gemm_tf32_kernel<0, 0, 0><<<dim3(DMODEL / 128, MROWS / 128), 256>>>(
            H, W2_i, T1, MROWS, DMODEL, DFF, nullptr, b2_i, 0);
        resid_ln_kernel<<<MROWS / 8, 256>>>(Q, -1, Q, T1,
                                            ln2_g + (size_t)i * DMODEL,
                                            ln2_b + (size_t)i * DMODEL);
    }

    // proj_out: fused BN+ReLU+transpose epilogue writes out[b][c][hw]
    gemm_tf32_kernel<0, 1, 0><<<dim3(CIN / 128, MROWS / 128), 256>>>(
        Q, WOT, out, MROWS, CIN, DMODEL, al2, be2, 1);
}